// round 1
// baseline (speedup 1.0000x reference)
#include <cuda_runtime.h>
#include <math.h>

// ---------------------------------------------------------------------------
// NUFFT type-2:  image(8,256,256) -> kdata(2,8,131072)
//   1) de-apodize (separable 1/FT(KB))          [folded into pass1 load]
//   2) centered zero-pad to 512x512, ifftshift, fft2
//        == FFT512 of zero-padded rows/cols, times i^{k1} * i^{k2}
//   3) 6x6 Kaiser-Bessel gather at non-uniform points, * dcf
// ---------------------------------------------------------------------------

#define IMN   256
#define G     512
#define B_    8
#define M_    131072           // 2^17
#define J_    6

// Scratch (device globals: allocation-free per harness rules)
__device__ float2 g_F2T[B_ * G * IMN];   // pass1 output, transposed: [b][k2][n1]  (8 MB)
__device__ float2 g_KGT[B_ * G * G];     // k-grid, transposed:       [b][k2][k1] (16 MB)
__device__ float  g_apod[IMN];

__device__ __forceinline__ float beta_f() {
    // BETA = pi * sqrt((J/OS)^2 * (OS-0.5)^2 - 0.8) = pi*sqrt(19.45), OS=2
    return (float)(3.141592653589793 * sqrt(19.45));
}

// Abramowitz & Stegun I0 (rel err ~2e-7)
__device__ __forceinline__ float bessi0f(float z) {
    if (z < 3.75f) {
        float t = z * z * (1.0f / 14.0625f);
        return 1.0f + t * (3.5156229f + t * (3.0899424f + t * (1.2067492f +
                     t * (0.2659732f + t * (0.0360768f + t * 0.0045813f)))));
    } else {
        float w = 3.75f / z;
        float p = 0.39894228f + w * (0.01328592f + w * (0.00225319f + w * (-0.00157565f +
                  w * (0.00916281f + w * (-0.02057706f + w * (0.02635537f +
                  w * (-0.01647633f + w * 0.00392377f)))))));
        return p * __expf(z) * rsqrtf(z);
    }
}

// Kaiser-Bessel kernel, support |u| < 3
__device__ __forceinline__ float kb(float u) {
    float x = u * (1.0f / 3.0f);          // 2u/J
    float t = 1.0f - x * x;
    if (t <= 0.0f) return 0.0f;
    return bessi0f(beta_f() * sqrtf(t));
}

// multiply by i^k
__device__ __forceinline__ float2 mul_ik(float2 v, int k) {
    switch (k & 3) {
        case 0:  return v;
        case 1:  return make_float2(-v.y,  v.x);
        case 2:  return make_float2(-v.x, -v.y);
        default: return make_float2( v.y, -v.x);
    }
}

// In-place 512-pt radix-2 DIT FFT over shared buffer (input pre-bit-reversed).
// 128 threads, 2 butterflies each per stage.
__device__ __forceinline__ void fft512(float2* sh, int tid) {
    #pragma unroll
    for (int half = 1; half <= 256; half <<= 1) {
        float step = -3.14159265358979f / (float)half;   // -2pi/(2*half)
        __syncthreads();
        #pragma unroll
        for (int t = tid; t < 256; t += 128) {
            int pos = t & (half - 1);
            int i0  = ((t & ~(half - 1)) << 1) | pos;
            int i1  = i0 + half;
            float s, c;
            __sincosf(step * (float)pos, &s, &c);
            float2 a = sh[i0];
            float2 b = sh[i1];
            float tr = c * b.x - s * b.y;
            float ti = c * b.y + s * b.x;
            sh[i0] = make_float2(a.x + tr, a.y + ti);
            sh[i1] = make_float2(a.x - tr, a.y - ti);
        }
    }
    __syncthreads();
}

// ---------------------------------------------------------------------------
__global__ void apod_kernel() {
    int n = threadIdx.x;                   // 256 threads
    float x   = (float)n - 128.0f;
    float arg = (float)(3.141592653589793) * 6.0f * x / 512.0f;
    float b   = beta_f();
    float t   = b * b - arg * arg;         // > 0 for this config
    float st  = sqrtf(t);
    float ph  = sinhf(st) / st;
    g_apod[n] = 1.0f / ph;
}

// Pass 1: FFT along n2 for each (b, n1). Loads image row * apod, zero-pads,
// writes i^{k2}-twiddled result transposed: g_F2T[b][k2][n1].
__global__ void pass1_kernel(const float* __restrict__ img) {
    int b  = blockIdx.x >> 8;
    int n1 = blockIdx.x & 255;
    int tid = threadIdx.x;
    __shared__ float2 sh[512];

    float a1 = g_apod[n1];
    const float* row = img + ((size_t)b * IMN + n1) * IMN;
    #pragma unroll
    for (int n = tid; n < 512; n += 128) {
        float v = 0.0f;
        if (n < 256) v = row[n] * g_apod[n] * a1;
        int br = __brev((unsigned)n) >> 23;
        sh[br] = make_float2(v, 0.0f);
    }
    fft512(sh, tid);
    #pragma unroll
    for (int k = tid; k < 512; k += 128) {
        g_F2T[((size_t)b * G + k) * IMN + n1] = mul_ik(sh[k], k);
    }
}

// Pass 2: FFT along n1 for each (b, k2). Contiguous load from g_F2T,
// writes i^{k1}-twiddled k-grid: g_KGT[b][k2][k1] (contiguous).
__global__ void pass2_kernel() {
    int b  = blockIdx.x >> 9;
    int k2 = blockIdx.x & 511;
    int tid = threadIdx.x;
    __shared__ float2 sh[512];

    const float2* src = g_F2T + ((size_t)b * G + k2) * IMN;
    #pragma unroll
    for (int n = tid; n < 512; n += 128) {
        float2 v = (n < 256) ? src[n] : make_float2(0.0f, 0.0f);
        int br = __brev((unsigned)n) >> 23;
        sh[br] = v;
    }
    fft512(sh, tid);
    float2* dst = g_KGT + ((size_t)b * G + k2) * G;
    #pragma unroll
    for (int k = tid; k < 512; k += 128) {
        dst[k] = mul_ik(sh[k], k);
    }
}

// Pass 3: 6x6 KB gather at non-uniform points.
__global__ void gather_kernel(const float* __restrict__ ktraj,
                              const float* __restrict__ dcf,
                              float* __restrict__ out) {
    int idx = blockIdx.x * blockDim.x + threadIdx.x;   // 0 .. B*M-1
    int b = idx >> 17;
    int m = idx & (M_ - 1);

    const float SC = (float)(512.0 / (2.0 * 3.141592653589793));
    float tm1 = ktraj[((size_t)b * 2)     * M_ + m] * SC;
    float tm2 = ktraj[((size_t)b * 2 + 1) * M_ + m] * SC;

    float f1 = floorf(tm1), f2 = floorf(tm2);
    float fr1 = tm1 - f1,   fr2 = tm2 - f2;
    int   b1 = (int)f1,     b2 = (int)f2;

    float w1[J_], w2[J_];
    #pragma unroll
    for (int j = 0; j < J_; j++) {
        w1[j] = kb(fr1 - (float)(j - 2));
        w2[j] = kb(fr2 - (float)(j - 2));
    }

    const float2* base = g_KGT + (size_t)b * G * G;
    float sre = 0.0f, sim = 0.0f;
    #pragma unroll
    for (int j2 = 0; j2 < J_; j2++) {
        int i2 = (b2 + j2 - 2 + 512) & 511;
        const float2* rowp = base + (size_t)i2 * G;
        float rre = 0.0f, rim = 0.0f;
        #pragma unroll
        for (int j1 = 0; j1 < J_; j1++) {
            int i1 = (b1 + j1 - 2 + 512) & 511;
            float2 v = __ldg(&rowp[i1]);
            rre = fmaf(w1[j1], v.x, rre);
            rim = fmaf(w1[j1], v.y, rim);
        }
        sre = fmaf(w2[j2], rre, sre);
        sim = fmaf(w2[j2], rim, sim);
    }

    float d = dcf[(size_t)b * M_ + m];
    out[idx]            = sre * d;   // (0, b, m)
    out[B_ * M_ + idx]  = sim * d;   // (1, b, m)
}

// ---------------------------------------------------------------------------
extern "C" void kernel_launch(void* const* d_in, const int* in_sizes, int n_in,
                              void* d_out, int out_size) {
    const float* image = (const float*)d_in[0];   // (8,256,256)
    const float* ktraj = (const float*)d_in[1];   // (8,2,131072)
    const float* dcf   = (const float*)d_in[2];   // (8,131072)
    float* out = (float*)d_out;                   // (2,8,131072)

    apod_kernel  <<<1, 256>>>();
    pass1_kernel <<<B_ * IMN, 128>>>(image);      // 2048 blocks
    pass2_kernel <<<B_ * G,   128>>>();           // 4096 blocks
    gather_kernel<<<(B_ * M_) / 256, 256>>>(ktraj, dcf, out);  // 4096 blocks
}

// round 2
// speedup vs baseline: 1.0333x; 1.0333x over previous
#include <cuda_runtime.h>
#include <math.h>

// ---------------------------------------------------------------------------
// NUFFT type-2:  image(8,256,256) -> kdata(2,8,131072)
//   1) de-apodize (separable 1/FT(KB))          [inlined in pass1]
//   2) centered zero-pad to 512x512, ifftshift, fft2
//        == FFT512 of zero-padded rows/cols, times i^{k1} * i^{k2}
//   3) 6x6 Kaiser-Bessel gather at non-uniform points, * dcf
//      -> vectorized: aligned float4 row loads + zero-padded 7-tap weights
// ---------------------------------------------------------------------------

#define IMN   256
#define G     512
#define B_    8
#define M_    131072           // 2^17
#define J_    6

// Scratch (device globals: allocation-free per harness rules)
__device__ float2 g_F2T[B_ * G * IMN];                  // pass1 out, [b][k2][n1] (8 MB)
__device__ __align__(16) float2 g_KGT[B_ * G * G];      // k-grid,    [b][k2][k1] (16 MB)

__device__ __forceinline__ float beta_f() {
    // BETA = pi * sqrt((J/OS)^2 * (OS-0.5)^2 - 0.8) = pi*sqrt(19.45), OS=2
    return (float)(3.141592653589793 * sqrt(19.45));
}

__device__ __forceinline__ float apod1(int n) {
    // 1/FT(KB) de-apodization coefficient for index n (0..255)
    float x   = (float)n - 128.0f;
    float arg = (float)(3.141592653589793) * 6.0f * x / 512.0f;
    float bb  = beta_f();
    float t   = bb * bb - arg * arg;      // > 0 for this config
    float st  = sqrtf(t);
    return st / sinhf(st);
}

// Abramowitz & Stegun I0 (rel err ~2e-7)
__device__ __forceinline__ float bessi0f(float z) {
    if (z < 3.75f) {
        float t = z * z * (1.0f / 14.0625f);
        return 1.0f + t * (3.5156229f + t * (3.0899424f + t * (1.2067492f +
                     t * (0.2659732f + t * (0.0360768f + t * 0.0045813f)))));
    } else {
        float w = 3.75f / z;
        float p = 0.39894228f + w * (0.01328592f + w * (0.00225319f + w * (-0.00157565f +
                  w * (0.00916281f + w * (-0.02057706f + w * (0.02635537f +
                  w * (-0.01647633f + w * 0.00392377f)))))));
        return p * __expf(z) * rsqrtf(z);
    }
}

// Kaiser-Bessel kernel, support |u| < 3
__device__ __forceinline__ float kb(float u) {
    float x = u * (1.0f / 3.0f);          // 2u/J
    float t = 1.0f - x * x;
    if (t <= 0.0f) return 0.0f;
    return bessi0f(beta_f() * sqrtf(t));
}

// multiply by i^k
__device__ __forceinline__ float2 mul_ik(float2 v, int k) {
    switch (k & 3) {
        case 0:  return v;
        case 1:  return make_float2(-v.y,  v.x);
        case 2:  return make_float2(-v.x, -v.y);
        default: return make_float2( v.y, -v.x);
    }
}

// In-place 512-pt radix-2 DIT FFT over shared buffer (input pre-bit-reversed).
// 128 threads, 2 butterflies each per stage.
__device__ __forceinline__ void fft512(float2* sh, int tid) {
    #pragma unroll
    for (int half = 1; half <= 256; half <<= 1) {
        float step = -3.14159265358979f / (float)half;   // -2pi/(2*half)
        __syncthreads();
        #pragma unroll
        for (int t = tid; t < 256; t += 128) {
            int pos = t & (half - 1);
            int i0  = ((t & ~(half - 1)) << 1) | pos;
            int i1  = i0 + half;
            float s, c;
            __sincosf(step * (float)pos, &s, &c);
            float2 a = sh[i0];
            float2 b = sh[i1];
            float tr = c * b.x - s * b.y;
            float ti = c * b.y + s * b.x;
            sh[i0] = make_float2(a.x + tr, a.y + ti);
            sh[i1] = make_float2(a.x - tr, a.y - ti);
        }
    }
    __syncthreads();
}

// ---------------------------------------------------------------------------
// Pass 1: FFT along n2 for each (b, n1). Loads image row * apod (both dims
// inlined), zero-pads, writes i^{k2}-twiddled result transposed to g_F2T.
__global__ void pass1_kernel(const float* __restrict__ img) {
    int b  = blockIdx.x >> 8;
    int n1 = blockIdx.x & 255;
    int tid = threadIdx.x;
    __shared__ float2 sh[512];

    float a1 = apod1(n1);
    const float* row = img + ((size_t)b * IMN + n1) * IMN;
    #pragma unroll
    for (int n = tid; n < 512; n += 128) {
        float v = 0.0f;
        if (n < 256) v = row[n] * apod1(n) * a1;
        int br = __brev((unsigned)n) >> 23;
        sh[br] = make_float2(v, 0.0f);
    }
    fft512(sh, tid);
    #pragma unroll
    for (int k = tid; k < 512; k += 128) {
        g_F2T[((size_t)b * G + k) * IMN + n1] = mul_ik(sh[k], k);
    }
}

// Pass 2: FFT along n1 for each (b, k2). Contiguous load from g_F2T,
// writes i^{k1}-twiddled k-grid: g_KGT[b][k2][k1] (contiguous).
__global__ void pass2_kernel() {
    int b  = blockIdx.x >> 9;
    int k2 = blockIdx.x & 511;
    int tid = threadIdx.x;
    __shared__ float2 sh[512];

    const float2* src = g_F2T + ((size_t)b * G + k2) * IMN;
    #pragma unroll
    for (int n = tid; n < 512; n += 128) {
        float2 v = (n < 256) ? src[n] : make_float2(0.0f, 0.0f);
        int br = __brev((unsigned)n) >> 23;
        sh[br] = v;
    }
    fft512(sh, tid);
    float2* dst = g_KGT + ((size_t)b * G + k2) * G;
    #pragma unroll
    for (int k = tid; k < 512; k += 128) {
        dst[k] = mul_ik(sh[k], k);
    }
}

// Pass 3: 6x6 KB gather at non-uniform points.
// Fast path: taps [b1-2 .. b1+3] don't wrap; align window down to an even
// complex index 'a' and gather 7 taps (one has zero weight) via
// 3x LDG.128 + 1x LDG.64 per row instead of 6x LDG.64 -> fewer L1 wavefronts.
__global__ void __launch_bounds__(256) gather_kernel(
        const float* __restrict__ ktraj,
        const float* __restrict__ dcf,
        float* __restrict__ out) {
    int idx = blockIdx.x * blockDim.x + threadIdx.x;   // 0 .. B*M-1
    int b = idx >> 17;
    int m = idx & (M_ - 1);

    const float SC = (float)(512.0 / (2.0 * 3.141592653589793));
    float tm1 = ktraj[((size_t)b * 2)     * M_ + m] * SC;
    float tm2 = ktraj[((size_t)b * 2 + 1) * M_ + m] * SC;

    float f1 = floorf(tm1), f2 = floorf(tm2);
    float fr1 = tm1 - f1,   fr2 = tm2 - f2;
    int   b1 = ((int)f1) & 511;     // wrapped base along contiguous dim
    int   b2 = (int)f2;             // row dim, wrapped per-row below

    float w1[J_], w2[J_];
    #pragma unroll
    for (int j = 0; j < J_; j++) {
        w1[j] = kb(fr1 - (float)(j - 2));
        w2[j] = kb(fr2 - (float)(j - 2));
    }

    const float2* base = g_KGT + (size_t)b * G * G;
    float sre = 0.0f, sim = 0.0f;

    if (b1 >= 2 && b1 <= 507) {
        int a   = (b1 - 2) & ~1;            // even, in [0, 504]
        int off = (b1 - 2) & 1;             // 0 or 1
        float wv0 = off ? 0.0f  : w1[0];
        float wv1 = off ? w1[0] : w1[1];
        float wv2 = off ? w1[1] : w1[2];
        float wv3 = off ? w1[2] : w1[3];
        float wv4 = off ? w1[3] : w1[4];
        float wv5 = off ? w1[4] : w1[5];
        float wv6 = off ? w1[5] : 0.0f;
        #pragma unroll
        for (int j2 = 0; j2 < J_; j2++) {
            int i2 = (b2 + j2 - 2) & 511;
            const float4* rp = (const float4*)(base + (size_t)i2 * G + a);
            float4 q0 = __ldg(rp);
            float4 q1 = __ldg(rp + 1);
            float4 q2 = __ldg(rp + 2);
            float2 q3 = __ldg((const float2*)(rp + 3));
            float rre = wv0 * q0.x;
            float rim = wv0 * q0.y;
            rre = fmaf(wv1, q0.z, rre);  rim = fmaf(wv1, q0.w, rim);
            rre = fmaf(wv2, q1.x, rre);  rim = fmaf(wv2, q1.y, rim);
            rre = fmaf(wv3, q1.z, rre);  rim = fmaf(wv3, q1.w, rim);
            rre = fmaf(wv4, q2.x, rre);  rim = fmaf(wv4, q2.y, rim);
            rre = fmaf(wv5, q2.z, rre);  rim = fmaf(wv5, q2.w, rim);
            rre = fmaf(wv6, q3.x, rre);  rim = fmaf(wv6, q3.y, rim);
            sre = fmaf(w2[j2], rre, sre);
            sim = fmaf(w2[j2], rim, sim);
        }
    } else {
        // wrap-around fallback (rare: ~2% of points)
        #pragma unroll
        for (int j2 = 0; j2 < J_; j2++) {
            int i2 = (b2 + j2 - 2) & 511;
            const float2* rowp = base + (size_t)i2 * G;
            float rre = 0.0f, rim = 0.0f;
            #pragma unroll
            for (int j1 = 0; j1 < J_; j1++) {
                int i1 = (b1 + j1 - 2) & 511;
                float2 v = __ldg(&rowp[i1]);
                rre = fmaf(w1[j1], v.x, rre);
                rim = fmaf(w1[j1], v.y, rim);
            }
            sre = fmaf(w2[j2], rre, sre);
            sim = fmaf(w2[j2], rim, sim);
        }
    }

    float d = dcf[(size_t)b * M_ + m];
    out[idx]           = sre * d;   // (0, b, m)
    out[B_ * M_ + idx] = sim * d;   // (1, b, m)
}

// ---------------------------------------------------------------------------
extern "C" void kernel_launch(void* const* d_in, const int* in_sizes, int n_in,
                              void* d_out, int out_size) {
    const float* image = (const float*)d_in[0];   // (8,256,256)
    const float* ktraj = (const float*)d_in[1];   // (8,2,131072)
    const float* dcf   = (const float*)d_in[2];   // (8,131072)
    float* out = (float*)d_out;                   // (2,8,131072)

    pass1_kernel <<<B_ * IMN, 128>>>(image);      // 2048 blocks
    pass2_kernel <<<B_ * G,   128>>>();           // 4096 blocks
    gather_kernel<<<(B_ * M_) / 256, 256>>>(ktraj, dcf, out);  // 4096 blocks
}